// round 14
// baseline (speedup 1.0000x reference)
#include <cuda_runtime.h>

// Problem constants
#define B_ 4
#define N_ 1024
#define H_ 64
#define D_ 64
#define FE_ 16
#define TOT (B_ * N_)
#define NPROD 64       // producer blocks (bids 0..63)
#define ZSLOTS 128     // output-GEMM slots (claimed by last 128 finishers)
#define ZROWS 32       // rows per zout slot

// Scratch (allocation-free __device__ globals)
__device__ float g_si[TOT];
__device__ float g_sj[TOT];
__device__ float g_rowsum[TOT];
// Monotonic counters — NEVER reset. Per launch: g_prod += 64, g_tick += 4096,
// g_rdone += 4096, so generation = ticket/4096 is exact and replay-safe.
__device__ unsigned g_prod  = 0;
__device__ unsigned g_tick  = 0;
__device__ unsigned g_rdone = 0;

// L2-coherent load (bypasses the non-coherent L1 path; REQUIRED for data
// written by other blocks during this kernel — __ldg here was the R13 bug).
__device__ __forceinline__ float ldcg(const float* p) {
    float v;
    asm volatile("ld.global.cg.f32 %0, [%1];" : "=f"(v) : "l"(p));
    return v;
}

// Bounded backoff spin: never hangs; a logic bug shows up as wrong output.
__device__ __forceinline__ void spin_until_ge(volatile unsigned* p, unsigned target) {
    unsigned ns = 64;
    for (unsigned i = 0; i < (1u << 20); ++i) {
        if ((int)(*p - target) >= 0) return;
        __nanosleep(ns);
        if (ns < 2048) ns <<= 1;
    }
}

union SMem {
    struct { float wfs[H_ * D_]; float u1[H_]; float u2[H_]; } p;            // 16.5 KB
    struct { float sev[N_]; float red[8]; } s;                               //  4.1 KB
    struct { float wT[H_ * 65]; float h0s[ZROWS * H_]; float red[16]; float tot; } z; // ~25 KB
};

// ---------------------------------------------------------------------------
// ONE fused kernel, grid 4096 x 256:
//  [bid<64] producer: u = w_fc^T a; si/sj for 64 rows; fence; g_prod++.
//           (waits on nothing -> always completes -> deadlock-free)
//  [all]    stream:   sev[j] = <e[row,j,:], a3> into smem — NO dependency.
//  [all]    tail:     ticket; wait g_prod; rowsum = sum_j exp(lrelu(
//                     si+sj[j]+sev[j])); fence; g_rdone++.
//  [last 128 tickets] wait g_rdone; out slice (fixed slot->rows map).
// ---------------------------------------------------------------------------
__global__ void __launch_bounds__(256) k_all(const float* __restrict__ h0,
                                             const float* __restrict__ e,
                                             const float* __restrict__ w_fc,
                                             const float* __restrict__ w_attn,
                                             float* __restrict__ out) {
    __shared__ SMem sm;
    __shared__ unsigned sh_ticket;

    const int t = threadIdx.x;
    const int bid = blockIdx.x;
    const int lane = t & 31;
    const int w = t >> 5;

    // ========================= producer (bid < 64) ==========================
    if (bid < NPROD) {
        const float4* w4 = reinterpret_cast<const float4*>(w_fc);
        float4* ws4 = reinterpret_cast<float4*>(sm.p.wfs);
#pragma unroll
        for (int k = t; k < (H_ * D_) / 4; k += 256) ws4[k] = w4[k];
        __syncthreads();

        if (t < 128) {                      // u[h] = sum_d wfs[d*64+h]*a[d]
            const int h = t & 63;
            const float* a = w_attn + (t >> 6) * D_;
            const float* col = sm.p.wfs + h;
            float acc = 0.f;
#pragma unroll
            for (int d = 0; d < D_; ++d)
                acc = fmaf(col[d * H_], __ldg(&a[d]), acc);
            if (t < 64) sm.p.u1[h] = acc; else sm.p.u2[h] = acc;
        }
        __syncthreads();

        const int g = t >> 4, q = t & 15;   // 16 groups x 16 threads
        const float4 w1 = reinterpret_cast<const float4*>(sm.p.u1)[q];
        const float4 w2 = reinterpret_cast<const float4*>(sm.p.u2)[q];
#pragma unroll
        for (int pass = 0; pass < 4; ++pass) {
            const int row = bid * 64 + pass * 16 + g;
            const float4 hv = __ldg(&reinterpret_cast<const float4*>(h0)[row * 16 + q]);
            float s1 = hv.x * w1.x, s2 = hv.x * w2.x;
            s1 = fmaf(hv.y, w1.y, s1); s2 = fmaf(hv.y, w2.y, s2);
            s1 = fmaf(hv.z, w1.z, s1); s2 = fmaf(hv.z, w2.z, s2);
            s1 = fmaf(hv.w, w1.w, s1); s2 = fmaf(hv.w, w2.w, s2);
#pragma unroll
            for (int o = 8; o; o >>= 1) {
                s1 += __shfl_down_sync(0xffffffffu, s1, o, 16);
                s2 += __shfl_down_sync(0xffffffffu, s2, o, 16);
            }
            if (q == 0) { g_sj[row] = s1; g_si[row] = s2; }
        }
        __syncthreads();
        if (t == 0) { __threadfence(); atomicAdd(&g_prod, 1u); }
        __syncthreads();        // before smem is repurposed
    }

    // ====================== stream phase (no gating) ========================
    {
        const int row = bid;
        const int fg = (lane & 3) * 4;
        const float af0 = __ldg(&w_attn[2 * D_ + fg + 0]);
        const float af1 = __ldg(&w_attn[2 * D_ + fg + 1]);
        const float af2 = __ldg(&w_attn[2 * D_ + fg + 2]);
        const float af3 = __ldg(&w_attn[2 * D_ + fg + 3]);
        const float4* e4 = reinterpret_cast<const float4*>(e) + (size_t)row * (N_ * 4);

#pragma unroll 8
        for (int idx4 = t; idx4 < N_ * 4; idx4 += 256) {
            const float4 v = __ldcs(&e4[idx4]);
            float p = v.x * af0;
            p = fmaf(v.y, af1, p);
            p = fmaf(v.z, af2, p);
            p = fmaf(v.w, af3, p);
            p += __shfl_xor_sync(0xffffffffu, p, 1);
            p += __shfl_xor_sync(0xffffffffu, p, 2);
            if ((t & 3) == 0) sm.s.sev[idx4 >> 2] = p;   // conflict-free
        }
    }
    __syncthreads();

    // ===================== tail: ticket, gate, exp, rowsum ==================
    if (t == 0) sh_ticket = atomicAdd(&g_tick, 1u);
    __syncthreads();
    const unsigned ticket = sh_ticket;
    const unsigned gen = ticket / (unsigned)TOT;

    if (t == 0) {
        spin_until_ge(&g_prod, (gen + 1u) * NPROD);   // producers long done
        __threadfence();
    }
    __syncthreads();

    {
        const int row = bid;
        const int b = row >> 10;
        const float si = ldcg(&g_si[row]);            // L2-coherent (cross-block)
        float acc = 0.f;
#pragma unroll
        for (int j = t; j < N_; j += 256) {
            float s = si + ldcg(&g_sj[b * N_ + j]) + sm.s.sev[j];
            s = (s >= 0.f) ? s : 0.01f * s;            // leaky_relu
            acc += __expf(s);                          // 1 exp per j (no 4x)
        }
#pragma unroll
        for (int o = 16; o; o >>= 1) acc += __shfl_down_sync(0xffffffffu, acc, o);
        if (lane == 0) sm.s.red[w] = acc;
        __syncthreads();
        if (t == 0) {
            float s = 0.f;
#pragma unroll
            for (int k = 0; k < 8; ++k) s += sm.s.red[k];
            g_rowsum[row] = s;
            __threadfence();
            atomicAdd(&g_rdone, 1u);
        }
    }

    // ============== zout: last 128 tickets compute out slices ===============
    const unsigned slot = ticket - gen * (unsigned)TOT;   // 0..4095 this launch
    if (slot < (unsigned)(TOT - ZSLOTS)) return;
    const int zidx = (int)slot - (TOT - ZSLOTS);          // 0..127 fixed->rows
    const int row0 = zidx * ZROWS;

    if (t == 0) {
        spin_until_ge(&g_rdone, (gen + 1u) * (unsigned)TOT);
        __threadfence();
    }
    __syncthreads();    // all threads gated; smem repurposed to .z

    {
        // batch total (rows of this slice share one batch since 32 | 1024)
        const int b = row0 >> 10;
        float a = 0.f;
#pragma unroll
        for (int k = t; k < N_; k += 256) a += ldcg(&g_rowsum[b * N_ + k]);
#pragma unroll
        for (int o = 16; o; o >>= 1) a += __shfl_down_sync(0xffffffffu, a, o);
        if (lane == 0) sm.z.red[w] = a;
        __syncthreads();
        if (t == 0) {
            float s = 0.f;
#pragma unroll
            for (int k = 0; k < 8; ++k) s += sm.z.red[k];
            sm.z.tot = s;
        }

        // stage w_fc transposed (pitch 65, conflict-free) + 32 h0 rows
#pragma unroll
        for (int idx = t; idx < H_ * D_; idx += 256) {
            const int d = idx >> 6, h = idx & 63;
            sm.z.wT[h * 65 + d] = w_fc[idx];
        }
#pragma unroll
        for (int idx = t; idx < ZROWS * H_; idx += 256)
            sm.z.h0s[idx] = __ldg(&h0[row0 * H_ + idx]);
        __syncthreads();

        const float inv = 1.0f / sm.z.tot;
        const int d = t & 63;
        const int rg = t >> 6;               // 0..3, 8 rows each
#pragma unroll
        for (int r8 = 0; r8 < 8; ++r8) {
            const int rl = rg * 8 + r8;
            const float* hr = &sm.z.h0s[rl * H_];
            float acc = 0.f;
#pragma unroll
            for (int h = 0; h < H_; ++h)
                acc = fmaf(hr[h], sm.z.wT[h * 65 + d], acc);
            const int row = row0 + rl;
            out[row * D_ + d] = ldcg(&g_rowsum[row]) * inv * acc;
        }
    }
}

// ---------------------------------------------------------------------------
extern "C" void kernel_launch(void* const* d_in, const int* in_sizes, int n_in,
                              void* d_out, int out_size) {
    const float* h0     = (const float*)d_in[0];   // (B,N,H)
    const float* e      = (const float*)d_in[1];   // (B,N,N,FE)
    const float* w_fc   = (const float*)d_in[2];   // (D,H)
    const float* w_attn = (const float*)d_in[3];   // (2D+FE,)
    float* out = (float*)d_out;                    // (B,N,D)

    k_all<<<TOT, 256>>>(h0, e, w_fc, w_attn, out);
}

// round 15
// speedup vs baseline: 1.0584x; 1.0584x over previous
#include <cuda_runtime.h>

// Problem constants
#define B_ 4
#define N_ 1024
#define H_ 64
#define D_ 64
#define FE_ 16
#define TOT (B_ * N_)
#define NPROD 64       // producer blocks (bids 0..63)
#define ZSLOTS 128     // output-GEMM slots (claimed by last 128 finishers)
#define ZROWS 32       // rows per zout slot

// Scratch (allocation-free __device__ globals)
__device__ float g_si[TOT];
__device__ float g_sj[TOT];
__device__ float g_rowsum[TOT];
// Monotonic counters — NEVER reset. Per launch: g_prod += 64, g_tick += 4096,
// g_rdone += 4096, so generation = ticket/4096 is exact and replay-safe.
__device__ unsigned g_prod  = 0;
__device__ unsigned g_tick  = 0;
__device__ unsigned g_rdone = 0;

// ---- fence-free coherence primitives (NO __threadfence -> NO CCTL.IVALL) ----
// L2-coherent data load/store for cross-block-produced values.
__device__ __forceinline__ float ldcg(const float* p) {
    float v;
    asm volatile("ld.global.cg.f32 %0, [%1];" : "=f"(v) : "l"(p));
    return v;
}
__device__ __forceinline__ void stcg(float* p, float v) {
    asm volatile("st.global.cg.f32 [%0], %1;" :: "l"(p), "f"(v));
}
// Release increment: orders this thread's prior memory ops (incl. those of
// block peers ordered via bar.sync) before the flag update. Native atomic,
// no separate membar -> no L1 flush.
__device__ __forceinline__ void release_inc(unsigned* p) {
    asm volatile("red.release.gpu.global.add.u32 [%0], 1;" :: "l"(p));
}
__device__ __forceinline__ unsigned ld_acquire(const unsigned* p) {
    unsigned v;
    asm volatile("ld.acquire.gpu.global.u32 %0, [%1];" : "=r"(v) : "l"(p));
    return v;
}
// Bounded backoff spin on an acquire load: never hangs (bug -> wrong output).
__device__ __forceinline__ void spin_until_ge(const unsigned* p, unsigned target,
                                              unsigned max_ns) {
    unsigned ns = 32;
    for (unsigned i = 0; i < (1u << 20); ++i) {
        if ((int)(ld_acquire(p) - target) >= 0) return;
        __nanosleep(ns);
        if (ns < max_ns) ns <<= 1;
    }
}

union SMem {
    struct { float wfs[H_ * D_]; float u1[H_]; float u2[H_]; } p;            // 16.5 KB
    struct { float sev[N_]; float red[8]; } s;                               //  4.1 KB
    struct { float wT[H_ * 65]; float h0s[ZROWS * H_]; float red[16]; float tot; } z; // ~25 KB
};

// ---------------------------------------------------------------------------
// ONE fused kernel, grid 4096 x 256 (R14 architecture, fences removed):
//  [bid<64] producer: u = w_fc^T a; si/sj (stcg); release g_prod++.
//  [all]    stream:   sev[j] = <e[row,j,:], a3> into smem — NO dependency.
//  [all]    tail:     ticket; acquire-wait g_prod; rowsum = sum_j exp(lrelu(
//                     si+sj[j]+sev[j])) (ldcg); stcg; release g_rdone++.
//  [last 128 tickets] acquire-wait g_rdone; out slice (fixed slot->rows map).
// ---------------------------------------------------------------------------
__global__ void __launch_bounds__(256) k_all(const float* __restrict__ h0,
                                             const float* __restrict__ e,
                                             const float* __restrict__ w_fc,
                                             const float* __restrict__ w_attn,
                                             float* __restrict__ out) {
    __shared__ SMem sm;
    __shared__ unsigned sh_ticket;

    const int t = threadIdx.x;
    const int bid = blockIdx.x;
    const int lane = t & 31;
    const int w = t >> 5;

    // ========================= producer (bid < 64) ==========================
    if (bid < NPROD) {
        const float4* w4 = reinterpret_cast<const float4*>(w_fc);
        float4* ws4 = reinterpret_cast<float4*>(sm.p.wfs);
#pragma unroll
        for (int k = t; k < (H_ * D_) / 4; k += 256) ws4[k] = w4[k];
        __syncthreads();

        if (t < 128) {                      // u[h] = sum_d wfs[d*64+h]*a[d]
            const int h = t & 63;
            const float* a = w_attn + (t >> 6) * D_;
            const float* col = sm.p.wfs + h;
            float acc = 0.f;
#pragma unroll
            for (int d = 0; d < D_; ++d)
                acc = fmaf(col[d * H_], __ldg(&a[d]), acc);
            if (t < 64) sm.p.u1[h] = acc; else sm.p.u2[h] = acc;
        }
        __syncthreads();

        const int g = t >> 4, q = t & 15;   // 16 groups x 16 threads
        const float4 w1 = reinterpret_cast<const float4*>(sm.p.u1)[q];
        const float4 w2 = reinterpret_cast<const float4*>(sm.p.u2)[q];
#pragma unroll
        for (int pass = 0; pass < 4; ++pass) {
            const int row = bid * 64 + pass * 16 + g;
            const float4 hv = __ldg(&reinterpret_cast<const float4*>(h0)[row * 16 + q]);
            float s1 = hv.x * w1.x, s2 = hv.x * w2.x;
            s1 = fmaf(hv.y, w1.y, s1); s2 = fmaf(hv.y, w2.y, s2);
            s1 = fmaf(hv.z, w1.z, s1); s2 = fmaf(hv.z, w2.z, s2);
            s1 = fmaf(hv.w, w1.w, s1); s2 = fmaf(hv.w, w2.w, s2);
#pragma unroll
            for (int o = 8; o; o >>= 1) {
                s1 += __shfl_down_sync(0xffffffffu, s1, o, 16);
                s2 += __shfl_down_sync(0xffffffffu, s2, o, 16);
            }
            if (q == 0) { stcg(&g_sj[row], s1); stcg(&g_si[row], s2); }
        }
        __syncthreads();                    // peers' stcg ordered before release
        if (t == 0) release_inc(&g_prod);
        __syncthreads();                    // before smem is repurposed
    }

    // ====================== stream phase (no gating) ========================
    {
        const int row = bid;
        const int fg = (lane & 3) * 4;
        const float af0 = __ldg(&w_attn[2 * D_ + fg + 0]);
        const float af1 = __ldg(&w_attn[2 * D_ + fg + 1]);
        const float af2 = __ldg(&w_attn[2 * D_ + fg + 2]);
        const float af3 = __ldg(&w_attn[2 * D_ + fg + 3]);
        const float4* e4 = reinterpret_cast<const float4*>(e) + (size_t)row * (N_ * 4);

#pragma unroll 8
        for (int idx4 = t; idx4 < N_ * 4; idx4 += 256) {
            const float4 v = __ldcs(&e4[idx4]);
            float p = v.x * af0;
            p = fmaf(v.y, af1, p);
            p = fmaf(v.z, af2, p);
            p = fmaf(v.w, af3, p);
            p += __shfl_xor_sync(0xffffffffu, p, 1);
            p += __shfl_xor_sync(0xffffffffu, p, 2);
            if ((t & 3) == 0) sm.s.sev[idx4 >> 2] = p;   // conflict-free
        }
    }
    __syncthreads();

    // ===================== tail: ticket, gate, exp, rowsum ==================
    if (t == 0) sh_ticket = atomicAdd(&g_tick, 1u);
    __syncthreads();
    const unsigned ticket = sh_ticket;
    const unsigned gen = ticket / (unsigned)TOT;

    if (t == 0) spin_until_ge(&g_prod, (gen + 1u) * NPROD, 512);
    __syncthreads();

    {
        const int row = bid;
        const int b = row >> 10;
        const float si = ldcg(&g_si[row]);            // L2-coherent
        float acc = 0.f;
#pragma unroll
        for (int j = t; j < N_; j += 256) {
            float s = si + ldcg(&g_sj[b * N_ + j]) + sm.s.sev[j];
            s = (s >= 0.f) ? s : 0.01f * s;            // leaky_relu
            acc += __expf(s);                          // 1 exp per j
        }
#pragma unroll
        for (int o = 16; o; o >>= 1) acc += __shfl_down_sync(0xffffffffu, acc, o);
        if (lane == 0) sm.s.red[w] = acc;
        __syncthreads();
        if (t == 0) {
            float s = 0.f;
#pragma unroll
            for (int k = 0; k < 8; ++k) s += sm.s.red[k];
            stcg(&g_rowsum[row], s);
            release_inc(&g_rdone);
        }
    }

    // ============== zout: last 128 tickets compute out slices ===============
    const unsigned slot = ticket - gen * (unsigned)TOT;   // 0..4095 this launch
    if (slot < (unsigned)(TOT - ZSLOTS)) return;
    const int zidx = (int)slot - (TOT - ZSLOTS);          // 0..127 fixed->rows
    const int row0 = zidx * ZROWS;

    if (t == 0) spin_until_ge(&g_rdone, (gen + 1u) * (unsigned)TOT, 256);
    __syncthreads();    // all threads gated; smem repurposed to .z

    {
        // batch total (rows of this slice share one batch since 32 | 1024)
        const int b = row0 >> 10;
        float a = 0.f;
#pragma unroll
        for (int k = t; k < N_; k += 256) a += ldcg(&g_rowsum[b * N_ + k]);
#pragma unroll
        for (int o = 16; o; o >>= 1) a += __shfl_down_sync(0xffffffffu, a, o);
        if (lane == 0) sm.z.red[w] = a;
        __syncthreads();
        if (t == 0) {
            float s = 0.f;
#pragma unroll
            for (int k = 0; k < 8; ++k) s += sm.z.red[k];
            sm.z.tot = s;
        }

        // stage w_fc transposed (pitch 65, conflict-free) + 32 h0 rows
#pragma unroll
        for (int idx = t; idx < H_ * D_; idx += 256) {
            const int d = idx >> 6, h = idx & 63;
            sm.z.wT[h * 65 + d] = w_fc[idx];
        }
#pragma unroll
        for (int idx = t; idx < ZROWS * H_; idx += 256)
            sm.z.h0s[idx] = __ldg(&h0[row0 * H_ + idx]);
        __syncthreads();

        const float inv = 1.0f / sm.z.tot;
        const int d = t & 63;
        const int rg = t >> 6;               // 0..3, 8 rows each
#pragma unroll
        for (int r8 = 0; r8 < 8; ++r8) {
            const int rl = rg * 8 + r8;
            const float* hr = &sm.z.h0s[rl * H_];
            float acc = 0.f;
#pragma unroll
            for (int h = 0; h < H_; ++h)
                acc = fmaf(hr[h], sm.z.wT[h * 65 + d], acc);
            const int row = row0 + rl;
            out[row * D_ + d] = ldcg(&g_rowsum[row]) * inv * acc;
        }
    }
}

// ---------------------------------------------------------------------------
extern "C" void kernel_launch(void* const* d_in, const int* in_sizes, int n_in,
                              void* d_out, int out_size) {
    const float* h0     = (const float*)d_in[0];   // (B,N,H)
    const float* e      = (const float*)d_in[1];   // (B,N,N,FE)
    const float* w_fc   = (const float*)d_in[2];   // (D,H)
    const float* w_attn = (const float*)d_in[3];   // (2D+FE,)
    float* out = (float*)d_out;                    // (B,N,D)

    k_all<<<TOT, 256>>>(h0, e, w_fc, w_attn, out);
}